// round 13
// baseline (speedup 1.0000x reference)
#include <cuda_runtime.h>
#include <cuda_fp16.h>
#include <cstdint>
#include <cstddef>

// Problem constants
#define BB    32
#define NN    4096
#define CC    558          // canonical columns
#define MM    559          // + dustbin
#define MP    576          // padded columns
#define NROWS (BB * NN)    // 131072
#define RPW   32           // rows per warp in fused kernels
#define SLOTS 128          // warps (= partial slots) per batch: NN/RPW

// Output layout (flattened tuple, fp32): full | soft | hard | dustbin
static const size_t FULL_OFF = 0;
static const size_t SOFT_OFF = (size_t)NROWS * MM;
static const size_t HARD_OFF = SOFT_OFF + (size_t)NROWS * CC;
static const size_t DUST_OFF = HARD_OFF + (size_t)NROWS;

// Scratch (__device__ globals; no allocations anywhere)
__device__ __half  g_E[(size_t)NROWS * MP];     // exp(scores) fp16, padded
__device__ float   g_u[NROWS];                  // u5 (polish) for k_final
__device__ float   g_mu[NROWS];
__device__ float   g_v[BB * MP];
__device__ float   g_lv[BB * MP];               // fp32 log(v5) for mimic final
__device__ float   g_cpart[(size_t)BB * SLOTS * MP];
__device__ float   g_cpartf[(size_t)BB * SLOTS * MP];
__device__ float   g_invnv[BB];
__device__ int     g_mtype;   // 0 = uint8, 1 = int32, 2 = float32

__device__ __forceinline__ int mask_at(const void* m, int i, int mt) {
    if (mt == 1) return ((const int*)m)[i] != 0;
    if (mt == 2) return ((const float*)m)[i] != 0.0f;
    return ((const unsigned char*)m)[i] != 0;
}

__device__ __forceinline__ float warpAllSum(float v) {
    #pragma unroll
    for (int o = 16; o > 0; o >>= 1) v += __shfl_xor_sync(0xffffffffu, v, o);
    return v;
}

// Kahan compensated add
__device__ __forceinline__ void kadd(float& a, float& c, float t) {
    float y = __fadd_rn(t, -c);
    float s = __fadd_rn(a, y);
    c = __fadd_rn(__fadd_rn(s, -a), -y);
    a = s;
}

// ---------------------------------------------------------------------------
// k_detect: classify mask dtype from byte-lane pattern (validated R5..R11).
// ---------------------------------------------------------------------------
__global__ void k_detect(const unsigned char* __restrict__ m) {
    __shared__ int s0, s1, s2, s3;
    if (threadIdx.x == 0) { s0 = 0; s1 = 0; s2 = 0; s3 = 0; }
    __syncthreads();
    int o0 = 0, o1 = 0, o2 = 0, o3 = 0;
    for (int i = threadIdx.x * 4; i < NROWS; i += 256 * 4) {
        uchar4 v = *(const uchar4*)(m + i);
        o0 |= v.x; o1 |= v.y; o2 |= v.z; o3 |= v.w;
    }
    atomicOr(&s0, o0); atomicOr(&s1, o1); atomicOr(&s2, o2); atomicOr(&s3, o3);
    __syncthreads();
    if (threadIdx.x == 0) {
        int mt;
        if (!s1 && !s2 && !s3)      mt = 1;  // int32
        else if (!s0 && !s1)        mt = 2;  // float32
        else                        mt = 0;  // uint8
        g_mtype = mt;
    }
}

// ---------------------------------------------------------------------------
// k_prep: 1 / num_visible per batch
// ---------------------------------------------------------------------------
__global__ __launch_bounds__(1024) void k_prep(const void* __restrict__ mask) {
    int b = blockIdx.x, t = threadIdx.x;
    int mt = g_mtype;
    int cnt = 0;
    #pragma unroll
    for (int i = 0; i < NN / 1024; i++) cnt += mask_at(mask, b * NN + t + i * 1024, mt);
    #pragma unroll
    for (int o = 16; o > 0; o >>= 1) cnt += __shfl_down_sync(0xffffffffu, cnt, o);
    __shared__ int s[32];
    int lane = t & 31, wid = t >> 5;
    if (lane == 0) s[wid] = cnt;
    __syncthreads();
    if (wid == 0) {
        int v = s[lane];
        #pragma unroll
        for (int o = 16; o > 0; o >>= 1) v += __shfl_down_sync(0xffffffffu, v, o);
        if (lane == 0) g_invnv[b] = 1.0f / (float)v;
    }
}

// ---------------------------------------------------------------------------
// k_exp_fused: one warp owns 32 rows. Per row: E=exp(s)->fp16, u1=mu/rowsum,
// accumulate u1*E into per-lane register column partials. One slot per warp.
// ---------------------------------------------------------------------------
__global__ __launch_bounds__(256) void k_exp_fused(const float* __restrict__ scores,
                                                   const void* __restrict__ mask,
                                                   const float* __restrict__ dust) {
    int w = threadIdx.x >> 5, l = threadIdx.x & 31;
    int gw = blockIdx.x * 8 + w;          // global warp 0..4095
    int row0 = gw * RPW;
    int b = row0 >> 12;
    int slot = gw & (SLOTS - 1);
    float ed = __expf(dust[0]);
    float inv = g_invnv[b];
    int mt = g_mtype;

    float a0[9], a1[9];
    #pragma unroll
    for (int k = 0; k < 9; k++) { a0[k] = 0.f; a1[k] = 0.f; }

    for (int r = 0; r < RPW; r++) {
        int row = row0 + r;
        const float* srow = scores + (size_t)row * CC;
        __half* erow = g_E + (size_t)row * MP;
        float e0v[9], e1v[9];
        float sum = 0.f;
        #pragma unroll
        for (int k = 0; k < 9; k++) {
            int i = l + 32 * k;
            float e0 = 0.f, e1 = 0.f;
            if (i < 279) {
                float2 s2 = *(const float2*)(srow + 2 * i);
                e0 = __expf(s2.x);
                e1 = __expf(s2.y);
            } else if (i == 279) {
                e0 = ed;                 // dustbin col 558; 559 pad
            }
            *(__half2*)(erow + 2 * i) = __floats2half2_rn(e0, e1);
            e0v[k] = e0; e1v[k] = e1;
            sum += e0 + e1;
        }
        sum = warpAllSum(sum);
        float muv = mask_at(mask, row, mt) ? inv : 0.f;
        if (l == 0) g_mu[row] = muv;
        float u = muv / sum;
        #pragma unroll
        for (int k = 0; k < 9; k++) { a0[k] += e0v[k] * u; a1[k] += e1v[k] * u; }
    }
    float* out = g_cpart + ((size_t)b * SLOTS + slot) * MP;
    #pragma unroll
    for (int k = 0; k < 9; k++) {
        int i = l + 32 * k;
        *(float2*)(out + 2 * i) = make_float2(a0[k], a1[k]);
    }
}

// ---------------------------------------------------------------------------
// k_col_red: reduce SLOTS partials -> v[m] = (1/559)/c[m]; pad cols -> 0.
// grid (9, BB) x 64 threads: 288 CTAs, thread owns one column, ascending-k
// order (bitwise identical to the previous single-CTA-per-batch version).
// ---------------------------------------------------------------------------
__global__ __launch_bounds__(64) void k_col_red() {
    int b = blockIdx.y;
    int m = blockIdx.x * 64 + threadIdx.x;   // 0..575
    const float* base = g_cpart + (size_t)b * SLOTS * MP + m;
    float s = 0.f;
    #pragma unroll 8
    for (int k = 0; k < SLOTS; k++) s += base[(size_t)k * MP];
    const float NU = 1.0f / 559.0f;
    g_v[b * MP + m] = (m < MM) ? (NU / s) : 0.f;
}

// ---------------------------------------------------------------------------
// k_fused_it (fp16 path, iterations 2..4): one warp owns 32 rows.
// Per row: u = mu/(E·v) then accumulate u*E into register column partials.
// ---------------------------------------------------------------------------
__global__ __launch_bounds__(256) void k_fused_it() {
    __shared__ float vs[MP];
    int w = threadIdx.x >> 5, l = threadIdx.x & 31;
    int gw = blockIdx.x * 8 + w;
    int row0 = gw * RPW;
    int b = row0 >> 12;
    int slot = gw & (SLOTS - 1);

    for (int f = threadIdx.x; f < MP; f += 256) vs[f] = g_v[b * MP + f];
    __syncthreads();

    float vr[24];
    #pragma unroll
    for (int j = 0; j < 8; j++) {
        vr[j]      = vs[8 * l + j];
        vr[8 + j]  = vs[256 + 8 * l + j];
        vr[16 + j] = (l < 8) ? vs[512 + 8 * l + j] : 0.f;
    }
    float acc[24];
    #pragma unroll
    for (int j = 0; j < 24; j++) acc[j] = 0.f;

    for (int r = 0; r < RPW; r++) {
        int row = row0 + r;
        const uint4* erow = (const uint4*)(g_E + (size_t)row * MP);
        uint4 q0 = erow[l];
        uint4 q1 = erow[32 + l];
        uint4 q2 = (l < 8) ? erow[64 + l] : make_uint4(0u, 0u, 0u, 0u);
        const __half2* h0 = (const __half2*)&q0;
        const __half2* h1 = (const __half2*)&q1;
        const __half2* h2 = (const __half2*)&q2;
        float d = 0.f;
        #pragma unroll
        for (int j = 0; j < 4; j++) {
            float2 f0 = __half22float2(h0[j]);
            float2 f1 = __half22float2(h1[j]);
            float2 f2 = __half22float2(h2[j]);
            d += f0.x * vr[2*j] + f0.y * vr[2*j+1];
            d += f1.x * vr[8+2*j] + f1.y * vr[8+2*j+1];
            d += f2.x * vr[16+2*j] + f2.y * vr[16+2*j+1];
        }
        d = warpAllSum(d);
        float u = __ldg(g_mu + row) / d;
        #pragma unroll
        for (int j = 0; j < 4; j++) {
            float2 f0 = __half22float2(h0[j]);
            float2 f1 = __half22float2(h1[j]);
            float2 f2 = __half22float2(h2[j]);
            acc[2*j]      += f0.x * u;  acc[2*j+1]    += f0.y * u;
            acc[8+2*j]    += f1.x * u;  acc[8+2*j+1]  += f1.y * u;
            acc[16+2*j]   += f2.x * u;  acc[16+2*j+1] += f2.y * u;
        }
    }
    float* out = g_cpart + ((size_t)b * SLOTS + slot) * MP;
    *(float4*)(out + 8 * l)       = make_float4(acc[0], acc[1], acc[2], acc[3]);
    *(float4*)(out + 8 * l + 4)   = make_float4(acc[4], acc[5], acc[6], acc[7]);
    *(float4*)(out + 256 + 8 * l)     = make_float4(acc[8], acc[9], acc[10], acc[11]);
    *(float4*)(out + 256 + 8 * l + 4) = make_float4(acc[12], acc[13], acc[14], acc[15]);
    if (l < 8) {
        *(float4*)(out + 512 + 8 * l)     = make_float4(acc[16], acc[17], acc[18], acc[19]);
        *(float4*)(out + 512 + 8 * l + 4) = make_float4(acc[20], acc[21], acc[22], acc[23]);
    }
}

// ---------------------------------------------------------------------------
// k_polish_fused: fp32 scores. Per row: u5 = mu/(exp(s)·v4), store u5;
// accumulate exp(s)*u5 into Kahan register column partials.
// ---------------------------------------------------------------------------
__global__ __launch_bounds__(256) void k_polish_fused(const float* __restrict__ scores,
                                                      const float* __restrict__ dust) {
    int w = threadIdx.x >> 5, l = threadIdx.x & 31;
    int gw = blockIdx.x * 8 + w;
    int row0 = gw * RPW;
    int b = row0 >> 12;
    int slot = gw & (SLOTS - 1);
    float ed = __expf(dust[0]);

    float vr0[9], vr1[9];
    #pragma unroll
    for (int k = 0; k < 9; k++) {
        int i = l + 32 * k;
        vr0[k] = g_v[b * MP + 2 * i];
        vr1[k] = g_v[b * MP + 2 * i + 1];   // pad cols are 0
    }
    float a0[9], c0[9], a1[9], c1[9];
    #pragma unroll
    for (int k = 0; k < 9; k++) { a0[k]=0.f; c0[k]=0.f; a1[k]=0.f; c1[k]=0.f; }

    for (int r = 0; r < RPW; r++) {
        int row = row0 + r;
        const float* srow = scores + (size_t)row * CC;
        float t0[9], t1[9];
        float d = 0.f;
        #pragma unroll
        for (int k = 0; k < 9; k++) {
            int i = l + 32 * k;
            float e0 = 0.f, e1 = 0.f;
            if (i < 279) {
                float2 s2 = *(const float2*)(srow + 2 * i);
                e0 = __expf(s2.x);
                e1 = __expf(s2.y);
            } else if (i == 279) {
                e0 = ed;
            }
            t0[k] = e0; t1[k] = e1;
            d += e0 * vr0[k] + e1 * vr1[k];
        }
        d = warpAllSum(d);
        float u = __ldg(g_mu + row) / d;
        if (l == 0) g_u[row] = u;
        #pragma unroll
        for (int k = 0; k < 9; k++) {
            kadd(a0[k], c0[k], t0[k] * u);
            kadd(a1[k], c1[k], t1[k] * u);
        }
    }
    float* out = g_cpartf + ((size_t)b * SLOTS + slot) * MP;
    #pragma unroll
    for (int k = 0; k < 9; k++) {
        int i = l + 32 * k;
        *(float2*)(out + 2 * i) = make_float2(a0[k], a1[k]);
    }
}

// ---------------------------------------------------------------------------
// k_col_redp: Kahan-reduce SLOTS fp32 partials -> v5, log_v5.
// grid (9, BB) x 64 threads (parallelized; same ascending-k order).
// ---------------------------------------------------------------------------
__global__ __launch_bounds__(64) void k_col_redp() {
    int b = blockIdx.y;
    int m = blockIdx.x * 64 + threadIdx.x;   // 0..575
    float s = 0.f, c = 0.f;
    const float* base = g_cpartf + (size_t)b * SLOTS * MP + m;
    if (m < MM) {
        #pragma unroll 8
        for (int k = 0; k < SLOTS; k++) kadd(s, c, base[(size_t)k * MP]);
    }
    const float NU = 1.0f / 559.0f;
    float v = (m < MM) ? (NU / s) : 0.f;
    g_v[b * MP + m]  = v;
    g_lv[b * MP + m] = (m < MM) ? logf(v) : 0.f;
}

// ---------------------------------------------------------------------------
// k_final: mimic reference arithmetic (bit-identical to validated R6..R11):
//   a = expf( fp32( fp32(s + log_u) + log_v ) )
// ---------------------------------------------------------------------------
__global__ __launch_bounds__(160) void k_final(const float* __restrict__ scores,
                                               const float* __restrict__ dust,
                                               float* __restrict__ out) {
    int row = blockIdx.x;
    int b = row >> 12;
    int t = threadIdx.x;
    float u  = __ldg(g_u + row);
    float lu = logf(u);             // u==0 (invisible) -> -inf -> outputs 0
    const float* srow  = scores + (size_t)row * CC;
    const float* lvrow = g_lv + b * MP;
    float* full = out + FULL_OFF + (size_t)row * MM;
    float* soft = out + SOFT_OFF + (size_t)row * CC;

    float bv = -1.f;
    int   bi = 0x7fffffff;
    #pragma unroll
    for (int p = 0; p < 2; p++) {
        int c2 = 2 * t + p * 288;
        if (t < 144 && c2 <= CC) {
            if (c2 < CC) {
                float2 s2 = *(const float2*)(srow + c2);
                float a0 = expf(__fadd_rn(__fadd_rn(s2.x, lu), lvrow[c2]));
                float a1 = expf(__fadd_rn(__fadd_rn(s2.y, lu), lvrow[c2 + 1]));
                full[c2]     = a0;
                full[c2 + 1] = a1;
                *(float2*)(soft + c2) = make_float2(a0, a1);
                if (a0 > bv) { bv = a0; bi = c2; }
                if (a1 > bv) { bv = a1; bi = c2 + 1; }
            } else {  // dustbin column
                float a = expf(__fadd_rn(__fadd_rn(dust[0], lu), lvrow[CC]));
                full[CC] = a;
                out[DUST_OFF + row] = a;
            }
        }
    }

    #pragma unroll
    for (int o = 16; o > 0; o >>= 1) {
        float ov = __shfl_down_sync(0xffffffffu, bv, o);
        int   oi = __shfl_down_sync(0xffffffffu, bi, o);
        if (ov > bv || (ov == bv && oi < bi)) { bv = ov; bi = oi; }
    }
    __shared__ float sv[32];
    __shared__ int   si[32];
    int lane = t & 31, wid = t >> 5;
    if (lane == 0) { sv[wid] = bv; si[wid] = bi; }
    __syncthreads();
    if (wid == 0) {
        int nw = blockDim.x >> 5;
        bv = (lane < nw) ? sv[lane] : -2.f;
        bi = (lane < nw) ? si[lane] : 0x7fffffff;
        #pragma unroll
        for (int o = 16; o > 0; o >>= 1) {
            float ov = __shfl_down_sync(0xffffffffu, bv, o);
            int   oi = __shfl_down_sync(0xffffffffu, bi, o);
            if (ov > bv || (ov == bv && oi < bi)) { bv = ov; bi = oi; }
        }
        if (lane == 0) out[HARD_OFF + row] = (float)bi;
    }
}

// ---------------------------------------------------------------------------
extern "C" void kernel_launch(void* const* d_in, const int* in_sizes, int n_in,
                              void* d_out, int out_size) {
    const float* scores = (const float*)d_in[0];
    const void*  mask   = (const void*)d_in[1];
    const float* dust   = (const float*)d_in[2];
    float* out = (float*)d_out;

    k_detect<<<1, 256>>>((const unsigned char*)mask);
    k_prep<<<BB, 1024>>>(mask);
    k_exp_fused<<<NROWS / (8 * RPW), 256>>>(scores, mask, dust); // E, u1, v1 partials
    k_col_red<<<dim3(9, BB), 64>>>();                            // v1
    for (int it = 0; it < 3; it++) {                             // u2..u4 + v2..v4
        k_fused_it<<<NROWS / (8 * RPW), 256>>>();
        k_col_red<<<dim3(9, BB), 64>>>();
    }
    k_polish_fused<<<NROWS / (8 * RPW), 256>>>(scores, dust);    // u5 + v5 partials
    k_col_redp<<<dim3(9, BB), 64>>>();                           // v5 + log_v5
    k_final<<<NROWS, 160>>>(scores, dust, out);
}

// round 16
// speedup vs baseline: 1.3057x; 1.3057x over previous
#include <cuda_runtime.h>
#include <cuda_fp16.h>
#include <cstdint>
#include <cstddef>

// Problem constants
#define BB    32
#define NN    4096
#define CC    558          // canonical columns
#define MM    559          // + dustbin
#define MP    576          // padded columns
#define NROWS (BB * NN)    // 131072
#define RPW   32           // rows per warp in fused kernels
#define SLOTS 128          // warps (= partial slots) per batch: NN/RPW

// Output layout (flattened tuple, fp32): full | soft | hard | dustbin
static const size_t FULL_OFF = 0;
static const size_t SOFT_OFF = (size_t)NROWS * MM;
static const size_t HARD_OFF = SOFT_OFF + (size_t)NROWS * CC;
static const size_t DUST_OFF = HARD_OFF + (size_t)NROWS;

// Scratch (__device__ globals; no allocations anywhere)
__device__ __half  g_E[(size_t)NROWS * MP];     // exp(scores) fp16, padded
__device__ float   g_u[NROWS];                  // u5 (polish) for k_final
__device__ float   g_mu[NROWS];
__device__ float   g_v[BB * MP];
__device__ float   g_lv[BB * MP];               // fp32 log(v5) for mimic final
__device__ float   g_cpart[(size_t)BB * SLOTS * MP];
__device__ float   g_cpartf[(size_t)BB * SLOTS * MP];
__device__ float   g_invnv[BB];
__device__ int     g_mtype;   // 0 = uint8, 1 = int32, 2 = float32

__device__ __forceinline__ int mask_at(const void* m, int i, int mt) {
    if (mt == 1) return ((const int*)m)[i] != 0;
    if (mt == 2) return ((const float*)m)[i] != 0.0f;
    return ((const unsigned char*)m)[i] != 0;
}

__device__ __forceinline__ float warpAllSum(float v) {
    #pragma unroll
    for (int o = 16; o > 0; o >>= 1) v += __shfl_xor_sync(0xffffffffu, v, o);
    return v;
}

// Kahan compensated add
__device__ __forceinline__ void kadd(float& a, float& c, float t) {
    float y = __fadd_rn(t, -c);
    float s = __fadd_rn(a, y);
    c = __fadd_rn(__fadd_rn(s, -a), -y);
    a = s;
}

// ---------------------------------------------------------------------------
// k_detect: classify mask dtype from byte-lane pattern (validated R5..R13).
// ---------------------------------------------------------------------------
__global__ void k_detect(const unsigned char* __restrict__ m) {
    __shared__ int s0, s1, s2, s3;
    if (threadIdx.x == 0) { s0 = 0; s1 = 0; s2 = 0; s3 = 0; }
    __syncthreads();
    int o0 = 0, o1 = 0, o2 = 0, o3 = 0;
    for (int i = threadIdx.x * 4; i < NROWS; i += 256 * 4) {
        uchar4 v = *(const uchar4*)(m + i);
        o0 |= v.x; o1 |= v.y; o2 |= v.z; o3 |= v.w;
    }
    atomicOr(&s0, o0); atomicOr(&s1, o1); atomicOr(&s2, o2); atomicOr(&s3, o3);
    __syncthreads();
    if (threadIdx.x == 0) {
        int mt;
        if (!s1 && !s2 && !s3)      mt = 1;  // int32
        else if (!s0 && !s1)        mt = 2;  // float32
        else                        mt = 0;  // uint8
        g_mtype = mt;
    }
}

// ---------------------------------------------------------------------------
// k_prep: 1 / num_visible per batch
// ---------------------------------------------------------------------------
__global__ __launch_bounds__(1024) void k_prep(const void* __restrict__ mask) {
    int b = blockIdx.x, t = threadIdx.x;
    int mt = g_mtype;
    int cnt = 0;
    #pragma unroll
    for (int i = 0; i < NN / 1024; i++) cnt += mask_at(mask, b * NN + t + i * 1024, mt);
    #pragma unroll
    for (int o = 16; o > 0; o >>= 1) cnt += __shfl_down_sync(0xffffffffu, cnt, o);
    __shared__ int s[32];
    int lane = t & 31, wid = t >> 5;
    if (lane == 0) s[wid] = cnt;
    __syncthreads();
    if (wid == 0) {
        int v = s[lane];
        #pragma unroll
        for (int o = 16; o > 0; o >>= 1) v += __shfl_down_sync(0xffffffffu, v, o);
        if (lane == 0) g_invnv[b] = 1.0f / (float)v;
    }
}

// ---------------------------------------------------------------------------
// k_exp_fused: one warp owns 32 rows. Per row: E=exp(s)->fp16, u1=mu/rowsum,
// accumulate u1*E into per-lane register column partials. One slot per warp.
// ---------------------------------------------------------------------------
__global__ __launch_bounds__(256) void k_exp_fused(const float* __restrict__ scores,
                                                   const void* __restrict__ mask,
                                                   const float* __restrict__ dust) {
    int w = threadIdx.x >> 5, l = threadIdx.x & 31;
    int gw = blockIdx.x * 8 + w;          // global warp 0..4095
    int row0 = gw * RPW;
    int b = row0 >> 12;
    int slot = gw & (SLOTS - 1);
    float ed = __expf(dust[0]);
    float inv = g_invnv[b];
    int mt = g_mtype;

    float a0[9], a1[9];
    #pragma unroll
    for (int k = 0; k < 9; k++) { a0[k] = 0.f; a1[k] = 0.f; }

    for (int r = 0; r < RPW; r++) {
        int row = row0 + r;
        const float* srow = scores + (size_t)row * CC;
        __half* erow = g_E + (size_t)row * MP;
        float e0v[9], e1v[9];
        float sum = 0.f;
        #pragma unroll
        for (int k = 0; k < 9; k++) {
            int i = l + 32 * k;
            float e0 = 0.f, e1 = 0.f;
            if (i < 279) {
                float2 s2 = *(const float2*)(srow + 2 * i);
                e0 = __expf(s2.x);
                e1 = __expf(s2.y);
            } else if (i == 279) {
                e0 = ed;                 // dustbin col 558; 559 pad
            }
            *(__half2*)(erow + 2 * i) = __floats2half2_rn(e0, e1);
            e0v[k] = e0; e1v[k] = e1;
            sum += e0 + e1;
        }
        sum = warpAllSum(sum);
        float muv = mask_at(mask, row, mt) ? inv : 0.f;
        if (l == 0) g_mu[row] = muv;
        float u = muv / sum;
        #pragma unroll
        for (int k = 0; k < 9; k++) { a0[k] += e0v[k] * u; a1[k] += e1v[k] * u; }
    }
    float* out = g_cpart + ((size_t)b * SLOTS + slot) * MP;
    #pragma unroll
    for (int k = 0; k < 9; k++) {
        int i = l + 32 * k;
        *(float2*)(out + 2 * i) = make_float2(a0[k], a1[k]);
    }
}

// ---------------------------------------------------------------------------
// k_col_red: reduce SLOTS partials -> v[m] = (1/559)/c[m]; pad cols -> 0.
// R11 launch shape (grid BB x 576 threads) + 4 independent accumulators with
// deep unroll for MLP ~32 (R13 showed this kernel is latency-bound).
// ---------------------------------------------------------------------------
__global__ __launch_bounds__(MP) void k_col_red() {
    int b = blockIdx.x;
    int m = threadIdx.x;
    const float* base = g_cpart + (size_t)b * SLOTS * MP + m;
    float s0 = 0.f, s1 = 0.f, s2 = 0.f, s3 = 0.f;
    #pragma unroll 8
    for (int k = 0; k < SLOTS; k += 4) {
        s0 += base[(size_t)k * MP];
        s1 += base[(size_t)(k + 1) * MP];
        s2 += base[(size_t)(k + 2) * MP];
        s3 += base[(size_t)(k + 3) * MP];
    }
    float s = (s0 + s1) + (s2 + s3);
    const float NU = 1.0f / 559.0f;
    g_v[b * MP + m] = (m < MM) ? (NU / s) : 0.f;
}

// ---------------------------------------------------------------------------
// k_fused_it (fp16 path, iterations 2..4): one warp owns 32 rows.
// Per row: u = mu/(E·v) then accumulate u*E into register column partials.
// ---------------------------------------------------------------------------
__global__ __launch_bounds__(256) void k_fused_it() {
    __shared__ float vs[MP];
    int w = threadIdx.x >> 5, l = threadIdx.x & 31;
    int gw = blockIdx.x * 8 + w;
    int row0 = gw * RPW;
    int b = row0 >> 12;
    int slot = gw & (SLOTS - 1);

    for (int f = threadIdx.x; f < MP; f += 256) vs[f] = g_v[b * MP + f];
    __syncthreads();

    float vr[24];
    #pragma unroll
    for (int j = 0; j < 8; j++) {
        vr[j]      = vs[8 * l + j];
        vr[8 + j]  = vs[256 + 8 * l + j];
        vr[16 + j] = (l < 8) ? vs[512 + 8 * l + j] : 0.f;
    }
    float acc[24];
    #pragma unroll
    for (int j = 0; j < 24; j++) acc[j] = 0.f;

    for (int r = 0; r < RPW; r++) {
        int row = row0 + r;
        const uint4* erow = (const uint4*)(g_E + (size_t)row * MP);
        uint4 q0 = erow[l];
        uint4 q1 = erow[32 + l];
        uint4 q2 = (l < 8) ? erow[64 + l] : make_uint4(0u, 0u, 0u, 0u);
        const __half2* h0 = (const __half2*)&q0;
        const __half2* h1 = (const __half2*)&q1;
        const __half2* h2 = (const __half2*)&q2;
        float d = 0.f;
        #pragma unroll
        for (int j = 0; j < 4; j++) {
            float2 f0 = __half22float2(h0[j]);
            float2 f1 = __half22float2(h1[j]);
            float2 f2 = __half22float2(h2[j]);
            d += f0.x * vr[2*j] + f0.y * vr[2*j+1];
            d += f1.x * vr[8+2*j] + f1.y * vr[8+2*j+1];
            d += f2.x * vr[16+2*j] + f2.y * vr[16+2*j+1];
        }
        d = warpAllSum(d);
        float u = __ldg(g_mu + row) / d;
        #pragma unroll
        for (int j = 0; j < 4; j++) {
            float2 f0 = __half22float2(h0[j]);
            float2 f1 = __half22float2(h1[j]);
            float2 f2 = __half22float2(h2[j]);
            acc[2*j]      += f0.x * u;  acc[2*j+1]    += f0.y * u;
            acc[8+2*j]    += f1.x * u;  acc[8+2*j+1]  += f1.y * u;
            acc[16+2*j]   += f2.x * u;  acc[16+2*j+1] += f2.y * u;
        }
    }
    float* out = g_cpart + ((size_t)b * SLOTS + slot) * MP;
    *(float4*)(out + 8 * l)       = make_float4(acc[0], acc[1], acc[2], acc[3]);
    *(float4*)(out + 8 * l + 4)   = make_float4(acc[4], acc[5], acc[6], acc[7]);
    *(float4*)(out + 256 + 8 * l)     = make_float4(acc[8], acc[9], acc[10], acc[11]);
    *(float4*)(out + 256 + 8 * l + 4) = make_float4(acc[12], acc[13], acc[14], acc[15]);
    if (l < 8) {
        *(float4*)(out + 512 + 8 * l)     = make_float4(acc[16], acc[17], acc[18], acc[19]);
        *(float4*)(out + 512 + 8 * l + 4) = make_float4(acc[20], acc[21], acc[22], acc[23]);
    }
}

// ---------------------------------------------------------------------------
// k_polish_fused: fp32 scores. Per row: u5 = mu/(exp(s)·v4), store u5;
// accumulate exp(s)*u5 into Kahan register column partials.
// ---------------------------------------------------------------------------
__global__ __launch_bounds__(256) void k_polish_fused(const float* __restrict__ scores,
                                                      const float* __restrict__ dust) {
    int w = threadIdx.x >> 5, l = threadIdx.x & 31;
    int gw = blockIdx.x * 8 + w;
    int row0 = gw * RPW;
    int b = row0 >> 12;
    int slot = gw & (SLOTS - 1);
    float ed = __expf(dust[0]);

    float vr0[9], vr1[9];
    #pragma unroll
    for (int k = 0; k < 9; k++) {
        int i = l + 32 * k;
        vr0[k] = g_v[b * MP + 2 * i];
        vr1[k] = g_v[b * MP + 2 * i + 1];   // pad cols are 0
    }
    float a0[9], c0[9], a1[9], c1[9];
    #pragma unroll
    for (int k = 0; k < 9; k++) { a0[k]=0.f; c0[k]=0.f; a1[k]=0.f; c1[k]=0.f; }

    for (int r = 0; r < RPW; r++) {
        int row = row0 + r;
        const float* srow = scores + (size_t)row * CC;
        float t0[9], t1[9];
        float d = 0.f;
        #pragma unroll
        for (int k = 0; k < 9; k++) {
            int i = l + 32 * k;
            float e0 = 0.f, e1 = 0.f;
            if (i < 279) {
                float2 s2 = *(const float2*)(srow + 2 * i);
                e0 = __expf(s2.x);
                e1 = __expf(s2.y);
            } else if (i == 279) {
                e0 = ed;
            }
            t0[k] = e0; t1[k] = e1;
            d += e0 * vr0[k] + e1 * vr1[k];
        }
        d = warpAllSum(d);
        float u = __ldg(g_mu + row) / d;
        if (l == 0) g_u[row] = u;
        #pragma unroll
        for (int k = 0; k < 9; k++) {
            kadd(a0[k], c0[k], t0[k] * u);
            kadd(a1[k], c1[k], t1[k] * u);
        }
    }
    float* out = g_cpartf + ((size_t)b * SLOTS + slot) * MP;
    #pragma unroll
    for (int k = 0; k < 9; k++) {
        int i = l + 32 * k;
        *(float2*)(out + 2 * i) = make_float2(a0[k], a1[k]);
    }
}

// ---------------------------------------------------------------------------
// k_col_redp: Kahan-reduce SLOTS fp32 partials -> v5, log_v5.
// R11 launch shape + 4 independent Kahan accumulators (MLP ~32), Kahan
// combine. Accuracy ~1e-9 — argmax-critical path protected.
// ---------------------------------------------------------------------------
__global__ __launch_bounds__(MP) void k_col_redp() {
    int b = blockIdx.x;
    int m = threadIdx.x;
    float a0=0.f,c0=0.f,a1=0.f,c1=0.f,a2=0.f,c2=0.f,a3=0.f,c3=0.f;
    const float* base = g_cpartf + (size_t)b * SLOTS * MP + m;
    if (m < MM) {
        #pragma unroll 8
        for (int k = 0; k < SLOTS; k += 4) {
            kadd(a0, c0, base[(size_t)k * MP]);
            kadd(a1, c1, base[(size_t)(k + 1) * MP]);
            kadd(a2, c2, base[(size_t)(k + 2) * MP]);
            kadd(a3, c3, base[(size_t)(k + 3) * MP]);
        }
    }
    float s = a0, c = c0;
    kadd(s, c, a1); kadd(s, c, a2); kadd(s, c, a3);
    const float NU = 1.0f / 559.0f;
    float v = (m < MM) ? (NU / s) : 0.f;
    g_v[b * MP + m]  = v;
    g_lv[b * MP + m] = (m < MM) ? logf(v) : 0.f;
}

// ---------------------------------------------------------------------------
// k_final: mimic reference arithmetic (bit-identical to validated R6..R13):
//   a = expf( fp32( fp32(s + log_u) + log_v ) )
// ---------------------------------------------------------------------------
__global__ __launch_bounds__(160) void k_final(const float* __restrict__ scores,
                                               const float* __restrict__ dust,
                                               float* __restrict__ out) {
    int row = blockIdx.x;
    int b = row >> 12;
    int t = threadIdx.x;
    float u  = __ldg(g_u + row);
    float lu = logf(u);             // u==0 (invisible) -> -inf -> outputs 0
    const float* srow  = scores + (size_t)row * CC;
    const float* lvrow = g_lv + b * MP;
    float* full = out + FULL_OFF + (size_t)row * MM;
    float* soft = out + SOFT_OFF + (size_t)row * CC;

    float bv = -1.f;
    int   bi = 0x7fffffff;
    #pragma unroll
    for (int p = 0; p < 2; p++) {
        int c2 = 2 * t + p * 288;
        if (t < 144 && c2 <= CC) {
            if (c2 < CC) {
                float2 s2 = *(const float2*)(srow + c2);
                float a0 = expf(__fadd_rn(__fadd_rn(s2.x, lu), lvrow[c2]));
                float a1 = expf(__fadd_rn(__fadd_rn(s2.y, lu), lvrow[c2 + 1]));
                full[c2]     = a0;
                full[c2 + 1] = a1;
                *(float2*)(soft + c2) = make_float2(a0, a1);
                if (a0 > bv) { bv = a0; bi = c2; }
                if (a1 > bv) { bv = a1; bi = c2 + 1; }
            } else {  // dustbin column
                float a = expf(__fadd_rn(__fadd_rn(dust[0], lu), lvrow[CC]));
                full[CC] = a;
                out[DUST_OFF + row] = a;
            }
        }
    }

    #pragma unroll
    for (int o = 16; o > 0; o >>= 1) {
        float ov = __shfl_down_sync(0xffffffffu, bv, o);
        int   oi = __shfl_down_sync(0xffffffffu, bi, o);
        if (ov > bv || (ov == bv && oi < bi)) { bv = ov; bi = oi; }
    }
    __shared__ float sv[32];
    __shared__ int   si[32];
    int lane = t & 31, wid = t >> 5;
    if (lane == 0) { sv[wid] = bv; si[wid] = bi; }
    __syncthreads();
    if (wid == 0) {
        int nw = blockDim.x >> 5;
        bv = (lane < nw) ? sv[lane] : -2.f;
        bi = (lane < nw) ? si[lane] : 0x7fffffff;
        #pragma unroll
        for (int o = 16; o > 0; o >>= 1) {
            float ov = __shfl_down_sync(0xffffffffu, bv, o);
            int   oi = __shfl_down_sync(0xffffffffu, bi, o);
            if (ov > bv || (ov == bv && oi < bi)) { bv = ov; bi = oi; }
        }
        if (lane == 0) out[HARD_OFF + row] = (float)bi;
    }
}

// ---------------------------------------------------------------------------
extern "C" void kernel_launch(void* const* d_in, const int* in_sizes, int n_in,
                              void* d_out, int out_size) {
    const float* scores = (const float*)d_in[0];
    const void*  mask   = (const void*)d_in[1];
    const float* dust   = (const float*)d_in[2];
    float* out = (float*)d_out;

    k_detect<<<1, 256>>>((const unsigned char*)mask);
    k_prep<<<BB, 1024>>>(mask);
    k_exp_fused<<<NROWS / (8 * RPW), 256>>>(scores, mask, dust); // E, u1, v1 partials
    k_col_red<<<BB, MP>>>();                                     // v1
    for (int it = 0; it < 3; it++) {                             // u2..u4 + v2..v4
        k_fused_it<<<NROWS / (8 * RPW), 256>>>();
        k_col_red<<<BB, MP>>>();
    }
    k_polish_fused<<<NROWS / (8 * RPW), 256>>>(scores, dust);    // u5 + v5 partials
    k_col_redp<<<BB, MP>>>();                                    // v5 + log_v5
    k_final<<<NROWS, 160>>>(scores, dust, out);
}

// round 17
// speedup vs baseline: 1.4531x; 1.1129x over previous
#include <cuda_runtime.h>
#include <cuda_fp16.h>
#include <cstdint>
#include <cstddef>

// Problem constants
#define BB    32
#define NN    4096
#define CC    558          // canonical columns
#define MM    559          // + dustbin
#define MP    576          // padded columns
#define NROWS (BB * NN)    // 131072
#define RPW   32           // rows per warp in fused kernels
#define SLOTC 16           // CTA-level partial slots per batch (512 CTAs / 32 batches)

// Output layout (flattened tuple, fp32): full | soft | hard | dustbin
static const size_t FULL_OFF = 0;
static const size_t SOFT_OFF = (size_t)NROWS * MM;
static const size_t HARD_OFF = SOFT_OFF + (size_t)NROWS * CC;
static const size_t DUST_OFF = HARD_OFF + (size_t)NROWS;

// Scratch (__device__ globals; no allocations anywhere)
__device__ __half  g_E[(size_t)NROWS * MP];     // exp(scores) fp16, padded
__device__ float   g_u[NROWS];                  // u5 (polish) for k_final
__device__ float   g_mu[NROWS];
__device__ float   g_v[BB * MP];
__device__ float   g_lv[BB * MP];               // fp32 log(v5) for mimic final
__device__ float   g_cpart[(size_t)BB * SLOTC * MP];
__device__ float   g_cpartf[(size_t)BB * SLOTC * MP];
__device__ float   g_invnv[BB];
__device__ int     g_mtype;   // 0 = uint8, 1 = int32, 2 = float32

__device__ __forceinline__ int mask_at(const void* m, int i, int mt) {
    if (mt == 1) return ((const int*)m)[i] != 0;
    if (mt == 2) return ((const float*)m)[i] != 0.0f;
    return ((const unsigned char*)m)[i] != 0;
}

__device__ __forceinline__ float warpAllSum(float v) {
    #pragma unroll
    for (int o = 16; o > 0; o >>= 1) v += __shfl_xor_sync(0xffffffffu, v, o);
    return v;
}

// Kahan compensated add (c holds pending over-count; true sum ~= a - c)
__device__ __forceinline__ void kadd(float& a, float& c, float t) {
    float y = __fadd_rn(t, -c);
    float s = __fadd_rn(a, y);
    c = __fadd_rn(__fadd_rn(s, -a), -y);
    a = s;
}

// ---------------------------------------------------------------------------
// k_detect: classify mask dtype from byte-lane pattern (validated R5..R16).
// ---------------------------------------------------------------------------
__global__ void k_detect(const unsigned char* __restrict__ m) {
    __shared__ int s0, s1, s2, s3;
    if (threadIdx.x == 0) { s0 = 0; s1 = 0; s2 = 0; s3 = 0; }
    __syncthreads();
    int o0 = 0, o1 = 0, o2 = 0, o3 = 0;
    for (int i = threadIdx.x * 4; i < NROWS; i += 256 * 4) {
        uchar4 v = *(const uchar4*)(m + i);
        o0 |= v.x; o1 |= v.y; o2 |= v.z; o3 |= v.w;
    }
    atomicOr(&s0, o0); atomicOr(&s1, o1); atomicOr(&s2, o2); atomicOr(&s3, o3);
    __syncthreads();
    if (threadIdx.x == 0) {
        int mt;
        if (!s1 && !s2 && !s3)      mt = 1;  // int32
        else if (!s0 && !s1)        mt = 2;  // float32
        else                        mt = 0;  // uint8
        g_mtype = mt;
    }
}

// ---------------------------------------------------------------------------
// k_prep: 1 / num_visible per batch
// ---------------------------------------------------------------------------
__global__ __launch_bounds__(1024) void k_prep(const void* __restrict__ mask) {
    int b = blockIdx.x, t = threadIdx.x;
    int mt = g_mtype;
    int cnt = 0;
    #pragma unroll
    for (int i = 0; i < NN / 1024; i++) cnt += mask_at(mask, b * NN + t + i * 1024, mt);
    #pragma unroll
    for (int o = 16; o > 0; o >>= 1) cnt += __shfl_down_sync(0xffffffffu, cnt, o);
    __shared__ int s[32];
    int lane = t & 31, wid = t >> 5;
    if (lane == 0) s[wid] = cnt;
    __syncthreads();
    if (wid == 0) {
        int v = s[lane];
        #pragma unroll
        for (int o = 16; o > 0; o >>= 1) v += __shfl_down_sync(0xffffffffu, v, o);
        if (lane == 0) g_invnv[b] = 1.0f / (float)v;
    }
}

// ---------------------------------------------------------------------------
// k_exp_fused: one warp owns 32 rows. Per row: E=exp(s)->fp16, u1=mu/rowsum,
// accumulate u1*E into register column partials; CTA combines 8 warps in
// smem (ascending warp order) -> ONE slot per CTA.
// ---------------------------------------------------------------------------
__global__ __launch_bounds__(256) void k_exp_fused(const float* __restrict__ scores,
                                                   const void* __restrict__ mask,
                                                   const float* __restrict__ dust) {
    __shared__ float sred[8 * MP];
    int w = threadIdx.x >> 5, l = threadIdx.x & 31;
    int gw = blockIdx.x * 8 + w;          // global warp 0..4095
    int row0 = gw * RPW;
    int b = row0 >> 12;
    float ed = __expf(dust[0]);
    float inv = g_invnv[b];
    int mt = g_mtype;

    float a0[9], a1[9];
    #pragma unroll
    for (int k = 0; k < 9; k++) { a0[k] = 0.f; a1[k] = 0.f; }

    for (int r = 0; r < RPW; r++) {
        int row = row0 + r;
        const float* srow = scores + (size_t)row * CC;
        __half* erow = g_E + (size_t)row * MP;
        float e0v[9], e1v[9];
        float sum = 0.f;
        #pragma unroll
        for (int k = 0; k < 9; k++) {
            int i = l + 32 * k;
            float e0 = 0.f, e1 = 0.f;
            if (i < 279) {
                float2 s2 = *(const float2*)(srow + 2 * i);
                e0 = __expf(s2.x);
                e1 = __expf(s2.y);
            } else if (i == 279) {
                e0 = ed;                 // dustbin col 558; 559 pad
            }
            *(__half2*)(erow + 2 * i) = __floats2half2_rn(e0, e1);
            e0v[k] = e0; e1v[k] = e1;
            sum += e0 + e1;
        }
        sum = warpAllSum(sum);
        float muv = mask_at(mask, row, mt) ? inv : 0.f;
        if (l == 0) g_mu[row] = muv;
        float u = muv / sum;
        #pragma unroll
        for (int k = 0; k < 9; k++) { a0[k] += e0v[k] * u; a1[k] += e1v[k] * u; }
    }
    float* so = sred + w * MP;
    #pragma unroll
    for (int k = 0; k < 9; k++) {
        int i = l + 32 * k;
        *(float2*)(so + 2 * i) = make_float2(a0[k], a1[k]);
    }
    __syncthreads();
    int slot = blockIdx.x & (SLOTC - 1);
    float* out = g_cpart + ((size_t)b * SLOTC + slot) * MP;
    for (int m = threadIdx.x; m < MP; m += 256) {
        float s = 0.f;
        #pragma unroll
        for (int ww = 0; ww < 8; ww++) s += sred[ww * MP + m];
        out[m] = s;
    }
}

// ---------------------------------------------------------------------------
// k_col_red: reduce SLOTC partials -> v[m] = (1/559)/c[m]; pad cols -> 0.
// 4 independent accumulators, full unroll (16 loads in flight).
// ---------------------------------------------------------------------------
__global__ __launch_bounds__(MP) void k_col_red() {
    int b = blockIdx.x;
    int m = threadIdx.x;
    const float* base = g_cpart + (size_t)b * SLOTC * MP + m;
    float s0 = 0.f, s1 = 0.f, s2 = 0.f, s3 = 0.f;
    #pragma unroll
    for (int k = 0; k < SLOTC; k += 4) {
        s0 += base[(size_t)k * MP];
        s1 += base[(size_t)(k + 1) * MP];
        s2 += base[(size_t)(k + 2) * MP];
        s3 += base[(size_t)(k + 3) * MP];
    }
    float s = (s0 + s1) + (s2 + s3);
    const float NU = 1.0f / 559.0f;
    g_v[b * MP + m] = (m < MM) ? (NU / s) : 0.f;
}

// ---------------------------------------------------------------------------
// k_fused_it (fp16 path, iterations 2..4): one warp owns 32 rows.
// Per row: u = mu/(E·v) then accumulate u*E into register column partials;
// CTA combines 8 warps in smem -> one slot.
// ---------------------------------------------------------------------------
__global__ __launch_bounds__(256) void k_fused_it() {
    __shared__ float vs[MP];
    __shared__ float sred[8 * MP];
    int w = threadIdx.x >> 5, l = threadIdx.x & 31;
    int gw = blockIdx.x * 8 + w;
    int row0 = gw * RPW;
    int b = row0 >> 12;

    for (int f = threadIdx.x; f < MP; f += 256) vs[f] = g_v[b * MP + f];
    __syncthreads();

    float vr[24];
    #pragma unroll
    for (int j = 0; j < 8; j++) {
        vr[j]      = vs[8 * l + j];
        vr[8 + j]  = vs[256 + 8 * l + j];
        vr[16 + j] = (l < 8) ? vs[512 + 8 * l + j] : 0.f;
    }
    float acc[24];
    #pragma unroll
    for (int j = 0; j < 24; j++) acc[j] = 0.f;

    for (int r = 0; r < RPW; r++) {
        int row = row0 + r;
        const uint4* erow = (const uint4*)(g_E + (size_t)row * MP);
        uint4 q0 = erow[l];
        uint4 q1 = erow[32 + l];
        uint4 q2 = (l < 8) ? erow[64 + l] : make_uint4(0u, 0u, 0u, 0u);
        const __half2* h0 = (const __half2*)&q0;
        const __half2* h1 = (const __half2*)&q1;
        const __half2* h2 = (const __half2*)&q2;
        float d = 0.f;
        #pragma unroll
        for (int j = 0; j < 4; j++) {
            float2 f0 = __half22float2(h0[j]);
            float2 f1 = __half22float2(h1[j]);
            float2 f2 = __half22float2(h2[j]);
            d += f0.x * vr[2*j] + f0.y * vr[2*j+1];
            d += f1.x * vr[8+2*j] + f1.y * vr[8+2*j+1];
            d += f2.x * vr[16+2*j] + f2.y * vr[16+2*j+1];
        }
        d = warpAllSum(d);
        float u = __ldg(g_mu + row) / d;
        #pragma unroll
        for (int j = 0; j < 4; j++) {
            float2 f0 = __half22float2(h0[j]);
            float2 f1 = __half22float2(h1[j]);
            float2 f2 = __half22float2(h2[j]);
            acc[2*j]      += f0.x * u;  acc[2*j+1]    += f0.y * u;
            acc[8+2*j]    += f1.x * u;  acc[8+2*j+1]  += f1.y * u;
            acc[16+2*j]   += f2.x * u;  acc[16+2*j+1] += f2.y * u;
        }
    }
    float* so = sred + w * MP;
    *(float4*)(so + 8 * l)       = make_float4(acc[0], acc[1], acc[2], acc[3]);
    *(float4*)(so + 8 * l + 4)   = make_float4(acc[4], acc[5], acc[6], acc[7]);
    *(float4*)(so + 256 + 8 * l)     = make_float4(acc[8], acc[9], acc[10], acc[11]);
    *(float4*)(so + 256 + 8 * l + 4) = make_float4(acc[12], acc[13], acc[14], acc[15]);
    if (l < 8) {
        *(float4*)(so + 512 + 8 * l)     = make_float4(acc[16], acc[17], acc[18], acc[19]);
        *(float4*)(so + 512 + 8 * l + 4) = make_float4(acc[20], acc[21], acc[22], acc[23]);
    }
    __syncthreads();
    int slot = blockIdx.x & (SLOTC - 1);
    float* out = g_cpart + ((size_t)b * SLOTC + slot) * MP;
    for (int m = threadIdx.x; m < MP; m += 256) {
        float s = 0.f;
        #pragma unroll
        for (int ww = 0; ww < 8; ww++) s += sred[ww * MP + m];
        out[m] = s;
    }
}

// ---------------------------------------------------------------------------
// k_polish_fused: fp32 scores. Per row: u5 = mu/(exp(s)·v4), store u5;
// Kahan register column partials; CTA Kahan-combines 8 warps (folded a-c).
// ---------------------------------------------------------------------------
__global__ __launch_bounds__(256) void k_polish_fused(const float* __restrict__ scores,
                                                      const float* __restrict__ dust) {
    __shared__ float sred[8 * MP];
    int w = threadIdx.x >> 5, l = threadIdx.x & 31;
    int gw = blockIdx.x * 8 + w;
    int row0 = gw * RPW;
    int b = row0 >> 12;
    float ed = __expf(dust[0]);

    float vr0[9], vr1[9];
    #pragma unroll
    for (int k = 0; k < 9; k++) {
        int i = l + 32 * k;
        vr0[k] = g_v[b * MP + 2 * i];
        vr1[k] = g_v[b * MP + 2 * i + 1];   // pad cols are 0
    }
    float a0[9], c0[9], a1[9], c1[9];
    #pragma unroll
    for (int k = 0; k < 9; k++) { a0[k]=0.f; c0[k]=0.f; a1[k]=0.f; c1[k]=0.f; }

    for (int r = 0; r < RPW; r++) {
        int row = row0 + r;
        const float* srow = scores + (size_t)row * CC;
        float t0[9], t1[9];
        float d = 0.f;
        #pragma unroll
        for (int k = 0; k < 9; k++) {
            int i = l + 32 * k;
            float e0 = 0.f, e1 = 0.f;
            if (i < 279) {
                float2 s2 = *(const float2*)(srow + 2 * i);
                e0 = __expf(s2.x);
                e1 = __expf(s2.y);
            } else if (i == 279) {
                e0 = ed;
            }
            t0[k] = e0; t1[k] = e1;
            d += e0 * vr0[k] + e1 * vr1[k];
        }
        d = warpAllSum(d);
        float u = __ldg(g_mu + row) / d;
        if (l == 0) g_u[row] = u;
        #pragma unroll
        for (int k = 0; k < 9; k++) {
            kadd(a0[k], c0[k], t0[k] * u);
            kadd(a1[k], c1[k], t1[k] * u);
        }
    }
    // fold compensation (true sum ~= a - c), stage in smem
    float* so = sred + w * MP;
    #pragma unroll
    for (int k = 0; k < 9; k++) {
        int i = l + 32 * k;
        *(float2*)(so + 2 * i) = make_float2(__fadd_rn(a0[k], -c0[k]),
                                             __fadd_rn(a1[k], -c1[k]));
    }
    __syncthreads();
    int slot = blockIdx.x & (SLOTC - 1);
    float* out = g_cpartf + ((size_t)b * SLOTC + slot) * MP;
    for (int m = threadIdx.x; m < MP; m += 256) {
        float s = 0.f, c = 0.f;
        #pragma unroll
        for (int ww = 0; ww < 8; ww++) kadd(s, c, sred[ww * MP + m]);
        out[m] = __fadd_rn(s, -c);
    }
}

// ---------------------------------------------------------------------------
// k_col_redp: Kahan-reduce SLOTC fp32 partials -> v5, log_v5.
// ---------------------------------------------------------------------------
__global__ __launch_bounds__(MP) void k_col_redp() {
    int b = blockIdx.x;
    int m = threadIdx.x;
    float s = 0.f, c = 0.f;
    const float* base = g_cpartf + (size_t)b * SLOTC * MP + m;
    if (m < MM) {
        #pragma unroll
        for (int k = 0; k < SLOTC; k++) kadd(s, c, base[(size_t)k * MP]);
    }
    s = __fadd_rn(s, -c);
    const float NU = 1.0f / 559.0f;
    float v = (m < MM) ? (NU / s) : 0.f;
    g_v[b * MP + m]  = v;
    g_lv[b * MP + m] = (m < MM) ? logf(v) : 0.f;
}

// ---------------------------------------------------------------------------
// k_final: warp per row, 8 rows/CTA. Mimic reference arithmetic per element
// (unchanged, validated R6..R16): a = expf(fp32(fp32(s+log_u)+log_v)).
// Warp argmax with first-index tie-break.
// ---------------------------------------------------------------------------
__global__ __launch_bounds__(256) void k_final(const float* __restrict__ scores,
                                               const float* __restrict__ dust,
                                               float* __restrict__ out) {
    int w = threadIdx.x >> 5, l = threadIdx.x & 31;
    int row = blockIdx.x * 8 + w;
    int b = row >> 12;
    float u  = __ldg(g_u + row);
    float lu = logf(u);             // u==0 (invisible) -> -inf -> outputs 0
    const float* srow  = scores + (size_t)row * CC;
    const float* lvrow = g_lv + b * MP;
    float* full = out + FULL_OFF + (size_t)row * MM;
    float* soft = out + SOFT_OFF + (size_t)row * CC;

    float bv = -1.f;
    int   bi = 0x7fffffff;
    #pragma unroll
    for (int k = 0; k < 9; k++) {
        int i = l + 32 * k;             // float2 index; cols {2i, 2i+1}
        if (i < 279) {
            int c2 = 2 * i;
            float2 s2 = *(const float2*)(srow + c2);
            float a0 = expf(__fadd_rn(__fadd_rn(s2.x, lu), lvrow[c2]));
            float a1 = expf(__fadd_rn(__fadd_rn(s2.y, lu), lvrow[c2 + 1]));
            full[c2]     = a0;          // full row base is 4B-aligned only
            full[c2 + 1] = a1;
            *(float2*)(soft + c2) = make_float2(a0, a1);
            // per-lane candidates ascend in column => strict '>' keeps first
            if (a0 > bv) { bv = a0; bi = c2; }
            if (a1 > bv) { bv = a1; bi = c2 + 1; }
        } else if (i == 279) {          // dustbin column 558
            float a = expf(__fadd_rn(__fadd_rn(dust[0], lu), lvrow[CC]));
            full[CC] = a;
            out[DUST_OFF + row] = a;
        }
    }

    // warp argmax, tie-break: smaller index wins (first occurrence)
    #pragma unroll
    for (int o = 16; o > 0; o >>= 1) {
        float ov = __shfl_down_sync(0xffffffffu, bv, o);
        int   oi = __shfl_down_sync(0xffffffffu, bi, o);
        if (ov > bv || (ov == bv && oi < bi)) { bv = ov; bi = oi; }
    }
    if (l == 0) out[HARD_OFF + row] = (float)bi;
}

// ---------------------------------------------------------------------------
extern "C" void kernel_launch(void* const* d_in, const int* in_sizes, int n_in,
                              void* d_out, int out_size) {
    const float* scores = (const float*)d_in[0];
    const void*  mask   = (const void*)d_in[1];
    const float* dust   = (const float*)d_in[2];
    float* out = (float*)d_out;

    k_detect<<<1, 256>>>((const unsigned char*)mask);
    k_prep<<<BB, 1024>>>(mask);
    k_exp_fused<<<NROWS / (8 * RPW), 256>>>(scores, mask, dust); // E, u1, v1 partials
    k_col_red<<<BB, MP>>>();                                     // v1
    for (int it = 0; it < 3; it++) {                             // u2..u4 + v2..v4
        k_fused_it<<<NROWS / (8 * RPW), 256>>>();
        k_col_red<<<BB, MP>>>();
    }
    k_polish_fused<<<NROWS / (8 * RPW), 256>>>(scores, dust);    // u5 + v5 partials
    k_col_redp<<<BB, MP>>>();                                    // v5 + log_v5
    k_final<<<NROWS / 8, 256>>>(scores, dust, out);
}